// round 2
// baseline (speedup 1.0000x reference)
#include <cuda_runtime.h>
#include <math.h>

// NaiveFourierKANLayer: y[b,j] = sum_{i,g} cos(x[b,i]*g)*W0[j,i,g] + sin(x[b,i]*g)*W1[j,i,g] + bias[j]
// B=1024, I=256, G=300, O=256.
// GEMM view: M=1024, N=256, K=2*I*G=153600. A generated on the fly via rotation
// recurrence (no MUFU in the hot path), B (coeffs, 157MB) streamed from HBM.

#define NB 1024
#define NI 256
#define NG 300
#define NO 256

#define BM 64          // batch rows per CTA
#define BN 32          // output cols per CTA
#define GK 20          // g-values per stage
#define KCH (2*GK)     // k-values per stage (cos/sin interleaved)
#define NCHUNK (NG/GK) // 15 stages per i

typedef unsigned long long u64;

// Packed dual-FMA: 2 fp32 FMAs per fma-pipe slot (sm_100+ f32x2 path).
__device__ __forceinline__ void ffma2(u64 &d, u64 a, u64 b) {
    asm volatile("fma.rn.f32x2 %0, %1, %2, %0;" : "+l"(d) : "l"(a), "l"(b));
}
__device__ __forceinline__ u64 bcast2(float v) {
    u64 r;
    unsigned int u = __float_as_uint(v);
    asm("mov.b64 %0, {%1, %1};" : "=l"(r) : "r"(u));
    return r;
}

__global__ void __launch_bounds__(256, 1)
fkan_kernel(const float* __restrict__ x,
            const float* __restrict__ fc,     // [2][O][I][G]
            const float* __restrict__ bias,   // [O]
            float* __restrict__ out)          // [B][O]
{
    // A: [k][row]  k = 2*(g-g0) + (0=cos,1=sin)
    __shared__ __align__(16) float As[KCH][BM];
    // B: [k][j]
    __shared__ __align__(16) float Bs[KCH][BN];

    const int tid = threadIdx.x;
    const int m0  = blockIdx.x * BM;
    const int n0  = blockIdx.y * BN;

    // --- A-generation mapping: 64 rows x 4 g-slots (stride-4 recurrence) ---
    const int grow  = tid & 63;
    const int gslot = tid >> 6;      // 0..3, handles g = gslot+1, gslot+5, ...

    // --- B-load mapping: 2 trig x 32 j x 4 g-lanes, 5 g each ---
    const int btt = tid >> 7;        // 0 = cos coeffs, 1 = sin coeffs
    const int bj  = (tid >> 2) & 31;
    const int bgq = tid & 3;

    // --- compute mapping: 16 col-groups x 16 row-pair-groups ---
    const int cg = tid & 15;         // cols {n0+2cg, n0+2cg+1}
    const int pg = tid >> 4;         // row pairs {2pg,2pg+1} and {2pg+32,2pg+33}

    u64 acc0 = 0ull, acc1 = 0ull, acc2 = 0ull, acc3 = 0ull;

    const float* xrow = x + (size_t)(m0 + grow) * NI;
    const float* bsrc = fc + ((size_t)(btt * NO + n0 + bj) * NI) * NG;

    for (int i = 0; i < NI; ++i) {
        // ---- init rotation state for this i ----
        const float t = xrow[i];
        float c1, s1;
        sincosf(t, &s1, &c1);              // accurate path, |t| small
        // advance to starting angle (gslot+1)*t
        float cc = c1, ss = s1;
        #pragma unroll 3
        for (int a = 0; a < gslot; ++a) {
            float nc = fmaf(cc, c1, -ss * s1);
            ss = fmaf(ss, c1, cc * s1);
            cc = nc;
        }
        // step rotation = angle 4t (exact double-angle from (c1,s1))
        const float c2 = fmaf(c1, c1, -s1 * s1);
        const float s2 = 2.f * s1 * c1;
        const float c4 = fmaf(c2, c2, -s2 * s2);
        const float s4 = 2.f * s2 * c2;

        const float* src_i = bsrc + (size_t)i * NG;

        for (int ch = 0; ch < NCHUNK; ++ch) {
            // ---- generate A tile: 5 (c,s) pairs per thread ----
            #pragma unroll
            for (int m = 0; m < 5; ++m) {
                const int gidx = gslot + 4 * m;
                As[2 * gidx][grow]     = cc;
                As[2 * gidx + 1][grow] = ss;
                float nc = fmaf(cc, c4, -ss * s4);
                ss = fmaf(ss, c4, cc * s4);
                cc = nc;
            }
            // ---- load B tile: 5 coeffs per thread ----
            #pragma unroll
            for (int m = 0; m < 5; ++m) {
                const int g = bgq + 4 * m;
                Bs[2 * g + btt][bj] = src_i[ch * GK + g];
            }
            __syncthreads();

            // ---- 64x32x40 FMA block, FFMA2-packed over row pairs ----
            #pragma unroll
            for (int k = 0; k < KCH; ++k) {
                const u64 a01 = *(const u64*)&As[k][2 * pg];        // rows 2pg,2pg+1
                const u64 a23 = *(const u64*)&As[k][2 * pg + 32];   // rows 2pg+32,+33
                const float2 bf = *(const float2*)&Bs[k][2 * cg];
                const u64 b0 = bcast2(bf.x);
                const u64 b1 = bcast2(bf.y);
                ffma2(acc0, a01, b0);
                ffma2(acc1, a01, b1);
                ffma2(acc2, a23, b0);
                ffma2(acc3, a23, b1);
            }
            __syncthreads();
        }
    }

    // ---- epilogue: unpack and add bias ----
    float2 v0, v1, v2, v3;
    v0 = *(float2*)&acc0; v1 = *(float2*)&acc1;
    v2 = *(float2*)&acc2; v3 = *(float2*)&acc3;

    const int r0 = m0 + 2 * pg;
    const int r2 = m0 + 2 * pg + 32;
    const int cA = n0 + 2 * cg;
    const int cB = cA + 1;
    const float bA = bias[cA];
    const float bB = bias[cB];

    out[(size_t)r0 * NO + cA]       = v0.x + bA;
    out[(size_t)(r0 + 1) * NO + cA] = v0.y + bA;
    out[(size_t)r0 * NO + cB]       = v1.x + bB;
    out[(size_t)(r0 + 1) * NO + cB] = v1.y + bB;
    out[(size_t)r2 * NO + cA]       = v2.x + bA;
    out[(size_t)(r2 + 1) * NO + cA] = v2.y + bA;
    out[(size_t)r2 * NO + cB]       = v3.x + bB;
    out[(size_t)(r2 + 1) * NO + cB] = v3.y + bB;
}

extern "C" void kernel_launch(void* const* d_in, const int* in_sizes, int n_in,
                              void* d_out, int out_size) {
    const float* x    = (const float*)d_in[0];
    const float* fc   = (const float*)d_in[1];
    const float* bias = (const float*)d_in[2];
    float* out        = (float*)d_out;

    dim3 grid(NB / BM, NO / BN);   // 16 x 8 = 128 CTAs, one wave on 148 SMs
    fkan_kernel<<<grid, 256>>>(x, fc, bias, out);
}

// round 4
// speedup vs baseline: 5.3903x; 5.3903x over previous
#include <cuda_runtime.h>
#include <cstdint>
#include <math.h>

// NaiveFourierKANLayer via warp-level bf16 mma.sync (HMMA), 3-term hi/lo split.
// y[b,j] = sum_{i,g} cos(x_bi*g)W0[j,i,g] + sin(x_bi*g)W1[j,i,g] + bias[j]
// GEMM: M=1024 N=256 K=153600. A generated by rotation recurrence.
// tcgen05 is unavailable (harness PTX target = compute_103, not 103a).

#define NI 256
#define NG 300
#define NO 256
#define SPLITK 8
#define IPC (NI/SPLITK)      // 32 i per CTA
#define NGC 10               // 32-g chunks per i (chunk 9 zero-padded)
#define NSTAGE (IPC*NGC)     // 320

#define RSB 144              // smem row pitch bytes (72 bf16) -> conflict-free ldmatrix
#define A_HI 0
#define A_LO 18432
#define B_HI 36864
#define B_LO 55296
#define STAGE_BYTES 73728
#define DYN_SMEM (2*STAGE_BYTES)   // 147456

__device__ float g_scratch[SPLITK * 1024 * 256];   // 8 MB split-K partials

// ---------------- helpers ----------------
__device__ __forceinline__ uint32_t smem_u32(const void* p) {
    uint32_t a;
    asm("{ .reg .u64 t; cvta.to.shared.u64 t, %1; cvt.u32.u64 %0, t; }" : "=r"(a) : "l"(p));
    return a;
}
// pack2(a,b): low bf16 = a (even k), high bf16 = b (odd k)
__device__ __forceinline__ uint32_t pack2(float a, float b) {
    uint32_t r;
    asm("cvt.rn.bf16x2.f32 %0, %2, %1;" : "=r"(r) : "f"(a), "f"(b));
    return r;
}
__device__ __forceinline__ float lo_f(uint32_t p) { return __uint_as_float(p << 16); }
__device__ __forceinline__ float hi_f(uint32_t p) { return __uint_as_float(p & 0xFFFF0000u); }

#define LDSM4(r0,r1,r2,r3,addr)                                              \
    asm volatile("ldmatrix.sync.aligned.m8n8.x4.shared.b16 {%0,%1,%2,%3}, [%4];" \
        : "=r"(r0), "=r"(r1), "=r"(r2), "=r"(r3) : "r"(addr))

#define MMA(d,a,b0,b1)                                                        \
    asm volatile("mma.sync.aligned.m16n8k16.row.col.f32.bf16.bf16.f32 "       \
        "{%0,%1,%2,%3},{%4,%5,%6,%7},{%8,%9},{%0,%1,%2,%3};"                  \
        : "+f"((d)[0]), "+f"((d)[1]), "+f"((d)[2]), "+f"((d)[3])              \
        : "r"((a)[0]), "r"((a)[1]), "r"((a)[2]), "r"((a)[3]), "r"(b0), "r"(b1))

extern __shared__ char dsmem[];

__global__ void __launch_bounds__(256, 1)
fkan_hmma(const float* __restrict__ x, const float* __restrict__ fc)
{
    const int tid  = threadIdx.x;
    const int lane = tid & 31;
    const int w    = tid >> 5;
    const int ks = blockIdx.x;            // split-K slice (i block)
    const int m0 = blockIdx.y * 128;      // batch-row tile
    const int n0 = blockIdx.z * 128;      // output-col tile

    const uint32_t smb = smem_u32(dsmem);

    // producer maps
    const int rr = tid >> 1, q = tid & 1;        // A-gen: row, g-half
    const int bt = tid >> 7, bj = tid & 127;     // B: trig part, j-row

    // mma maps: 8 warps = 2(M) x 4(N); warp tile 64x32
    const int wm = w & 1, wn = w >> 1;
    // ldmatrix lane address bases (see fragment mapping in PTX ISA)
    const uint32_t aoff = (uint32_t)(wm*64 + (lane & 7) + ((lane >> 3) & 1)*8) * RSB
                        + (uint32_t)(lane >> 4) * 16;
    const uint32_t boff = (uint32_t)(wn*32 + (lane & 7) + (lane >> 4)*8) * RSB
                        + (uint32_t)((lane >> 3) & 1) * 16;

    float acc[4][4][4];
    #pragma unroll
    for (int a = 0; a < 4; ++a)
        #pragma unroll
        for (int b = 0; b < 4; ++b)
            #pragma unroll
            for (int c = 0; c < 4; ++c) acc[a][b][c] = 0.f;

    const float* xcol  = x + (size_t)(m0 + rr) * NI + ks * IPC;
    const float* bbase = fc + ((size_t)(bt * NO + n0 + bj) * NI + ks * IPC) * NG;

    // B stage prefetch registers (32 floats)
    float4 bf[8];
    {
        const float* p = bbase;            // ii=0, gc=0
        #pragma unroll
        for (int q4 = 0; q4 < 8; ++q4) bf[q4] = *(const float4*)(p + q4*4);
    }

    int it = 0;
    for (int ii = 0; ii < IPC; ++ii) {
        // rotation setup for this i
        const float t = xcol[ii];
        float s1, c1;
        sincosf(t, &s1, &c1);
        const float c2 = fmaf(c1, c1, -(s1*s1)), s2 = 2.f*c1*s1;
        const float c4 = fmaf(c2, c2, -(s2*s2)), s4 = 2.f*c2*s2;
        const float c8 = fmaf(c4, c4, -(s4*s4)), s8 = 2.f*c4*s4;
        const float c16 = fmaf(c8, c8, -(s8*s8)), s16 = 2.f*c8*s8;
        // state at angle (q*16 + 1)*t
        float cc, ss;
        if (q) { cc = fmaf(c1, c16, -(s1*s16)); ss = fmaf(s1, c16, c1*s16); }
        else   { cc = c1; ss = s1; }

        for (int gc = 0; gc < NGC; ++gc, ++it) {
            char* sm = dsmem + (it & 1) * STAGE_BYTES;

            // ---- STS B (from prefetched regs): k = bt*32 + g ----
            {
                const float* bv = (const float*)bf;
                #pragma unroll
                for (int pp = 0; pp < 16; ++pp) {
                    const float a = bv[2*pp], b = bv[2*pp+1];
                    const uint32_t hp = pack2(a, b);
                    const uint32_t lp = pack2(a - lo_f(hp), b - hi_f(hp));
                    const uint32_t off = (uint32_t)bj * RSB + (uint32_t)(bt*32 + 2*pp) * 2;
                    *(uint32_t*)(sm + B_HI + off) = hp;
                    *(uint32_t*)(sm + B_LO + off) = lp;
                }
            }
            // ---- generate + STS A: 8 adjacent-g pairs; cos at k=gl, sin at k=32+gl ----
            #pragma unroll
            for (int m = 0; m < 8; ++m) {
                const int gl = q*16 + 2*m;
                const int gg = gc*32 + gl;          // harmonic gg+1
                float ce = cc, se = ss;
                float co = fmaf(cc, c1, -(ss*s1));
                float so = fmaf(ss, c1,  cc*s1);
                if (gg     >= NG) { ce = 0.f; se = 0.f; }
                if (gg + 1 >= NG) { co = 0.f; so = 0.f; }
                const uint32_t chp = pack2(ce, co);
                const uint32_t clp = pack2(ce - lo_f(chp), co - hi_f(chp));
                const uint32_t shp = pack2(se, so);
                const uint32_t slp = pack2(se - lo_f(shp), so - hi_f(shp));
                const uint32_t offc = (uint32_t)rr * RSB + (uint32_t)gl * 2;
                *(uint32_t*)(sm + A_HI + offc)      = chp;
                *(uint32_t*)(sm + A_LO + offc)      = clp;
                *(uint32_t*)(sm + A_HI + offc + 64) = shp;
                *(uint32_t*)(sm + A_LO + offc + 64) = slp;
                // advance pair start by 2t
                const float nc = fmaf(cc, c2, -(ss*s2));
                ss = fmaf(ss, c2, cc*s2); cc = nc;
            }
            // jump +16t over the other half to next 32-g chunk
            { const float nc = fmaf(cc, c16, -(ss*s16));
              ss = fmaf(ss, c16, cc*s16); cc = nc; }

            __syncthreads();

            // ---- prefetch next stage's B (hidden under HMMA) ----
            if (it + 1 < NSTAGE) {
                const int nit = it + 1;
                const int nii = nit / NGC, ngc = nit % NGC;
                const float* p = bbase + (size_t)nii * NG + ngc * 32;
                #pragma unroll
                for (int q4 = 0; q4 < 8; ++q4) {
                    const int gg = ngc*32 + q4*4;
                    bf[q4] = (gg < NG) ? *(const float4*)(p + q4*4)
                                       : make_float4(0.f, 0.f, 0.f, 0.f);
                }
            }

            // ---- consume: 4 K-steps x (4 mf x 4 n8) x 3 hi/lo terms ----
            const uint32_t pA = smb + (uint32_t)(it & 1) * STAGE_BYTES + aoff;          // A_HI=0
            const uint32_t pB = smb + (uint32_t)(it & 1) * STAGE_BYTES + B_HI + boff;
            #pragma unroll
            for (int kk = 0; kk < 4; ++kk) {
                uint32_t bh[8], bl[8];
                LDSM4(bh[0], bh[1], bh[2], bh[3], pB + kk*32);
                LDSM4(bh[4], bh[5], bh[6], bh[7], pB + 16*RSB + kk*32);
                LDSM4(bl[0], bl[1], bl[2], bl[3], pB + (B_LO - B_HI) + kk*32);
                LDSM4(bl[4], bl[5], bl[6], bl[7], pB + (B_LO - B_HI) + 16*RSB + kk*32);
                #pragma unroll
                for (int mf = 0; mf < 4; ++mf) {
                    uint32_t ah[4], al[4];
                    LDSM4(ah[0], ah[1], ah[2], ah[3], pA + mf*(16*RSB) + kk*32);
                    LDSM4(al[0], al[1], al[2], al[3], pA + A_LO + mf*(16*RSB) + kk*32);
                    #pragma unroll
                    for (int f = 0; f < 4; ++f) {
                        const int bi = (f >> 1)*4 + (f & 1)*2;
                        MMA(acc[mf][f], ah, bh[bi], bh[bi+1]);   // AhiBhi
                        MMA(acc[mf][f], ah, bl[bi], bl[bi+1]);   // AhiBlo
                        MMA(acc[mf][f], al, bh[bi], bh[bi+1]);   // AloBhi
                    }
                }
            }
            // single barrier per stage: next STS targets the other buffer;
            // buffer reuse at stage s+2 is ordered by bar(s+1) after mma(s).
        }
    }

    // ---- epilogue: accumulators -> split-K scratch ----
    float* dst = g_scratch + ((size_t)ks << 18);
    #pragma unroll
    for (int mf = 0; mf < 4; ++mf) {
        const int r = m0 + wm*64 + mf*16 + (lane >> 2);
        #pragma unroll
        for (int f = 0; f < 4; ++f) {
            const int c = n0 + wn*32 + f*8 + (lane & 3)*2;
            float2 v0; v0.x = acc[mf][f][0]; v0.y = acc[mf][f][1];
            float2 v1; v1.x = acc[mf][f][2]; v1.y = acc[mf][f][3];
            *(float2*)(dst + (size_t)r * NO + c)       = v0;
            *(float2*)(dst + (size_t)(r + 8) * NO + c) = v1;
        }
    }
}

__global__ void __launch_bounds__(512, 1)
fkan_reduce(const float* __restrict__ bias, float* __restrict__ out)
{
    const int idx = blockIdx.x * 512 + threadIdx.x;   // 512 blocks -> 262144
    float a = bias[idx & 255];
    #pragma unroll
    for (int k = 0; k < SPLITK; ++k)
        a += g_scratch[((size_t)k << 18) + idx];
    out[idx] = a;
}

extern "C" void kernel_launch(void* const* d_in, const int* in_sizes, int n_in,
                              void* d_out, int out_size) {
    const float* x    = (const float*)d_in[0];
    const float* fc   = (const float*)d_in[1];
    const float* bias = (const float*)d_in[2];
    float* out        = (float*)d_out;

    cudaFuncSetAttribute(fkan_hmma, cudaFuncAttributeMaxDynamicSharedMemorySize, DYN_SMEM);
    fkan_hmma<<<dim3(SPLITK, 8, 2), 256, DYN_SMEM>>>(x, fc);
    fkan_reduce<<<512, 512>>>(bias, out);
}